// round 2
// baseline (speedup 1.0000x reference)
#include <cuda_runtime.h>

#define NUM_FACES 13776
#define MAXC 8
#define EPSF 1e-8f
#define SIGMA 0.5f

// ---- device scratch (no allocations allowed) ----
__device__ float4 g_bbmin[NUM_FACES];   // (minx,miny,minz, face_id0 as float bits)
__device__ float4 g_bbmax[NUM_FACES];   // (maxx,maxy,maxz, face_id1 as float bits)
__device__ int    g_f2[NUM_FACES];      // face_id2
__device__ float  g_tri[NUM_FACES * 9]; // 3 verts x 3 coords per face
__device__ double g_accum;

// ---------------------------------------------------------------------------
// Kernel A: per-face gather + AABB, zero accumulator
// ---------------------------------------------------------------------------
__global__ void setup_kernel(const float* __restrict__ verts,
                             const int*   __restrict__ faces) {
    int f = blockIdx.x * blockDim.x + threadIdx.x;
    if (f == 0) g_accum = 0.0;
    if (f >= NUM_FACES) return;

    int i0 = faces[3 * f + 0];
    int i1 = faces[3 * f + 1];
    int i2 = faces[3 * f + 2];

    float x0 = verts[3 * i0 + 0], y0 = verts[3 * i0 + 1], z0 = verts[3 * i0 + 2];
    float x1 = verts[3 * i1 + 0], y1 = verts[3 * i1 + 1], z1 = verts[3 * i1 + 2];
    float x2 = verts[3 * i2 + 0], y2 = verts[3 * i2 + 1], z2 = verts[3 * i2 + 2];

    float* t = &g_tri[f * 9];
    t[0] = x0; t[1] = y0; t[2] = z0;
    t[3] = x1; t[4] = y1; t[5] = z1;
    t[6] = x2; t[7] = y2; t[8] = z2;

    float mnx = fminf(x0, fminf(x1, x2));
    float mny = fminf(y0, fminf(y1, y2));
    float mnz = fminf(z0, fminf(z1, z2));
    float mxx = fmaxf(x0, fmaxf(x1, x2));
    float mxy = fmaxf(y0, fmaxf(y1, y2));
    float mxz = fmaxf(z0, fmaxf(z1, z2));

    g_bbmin[f] = make_float4(mnx, mny, mnz, __int_as_float(i0));
    g_bbmax[f] = make_float4(mxx, mxy, mxz, __int_as_float(i1));
    g_f2[f]    = i2;
}

// ---------------------------------------------------------------------------
// Cone-field penalty of src triangle evaluated at the 3 vertices of pts tri.
// Mirrors the reference math exactly (float32, PENALIZE_OUTSIDE, not P2P).
// ---------------------------------------------------------------------------
__device__ __forceinline__ float cone_penalty(const float* __restrict__ A,
                                              const float* __restrict__ P) {
    // src verts
    float a0x = A[0], a0y = A[1], a0z = A[2];
    float a1x = A[3], a1y = A[4], a1z = A[5];
    float a2x = A[6], a2y = A[7], a2z = A[8];

    float e0x = a1x - a0x, e0y = a1y - a0y, e0z = a1z - a0z;
    float e1x = a2x - a0x, e1y = a2y - a0y, e1z = a2z - a0z;

    float nx = e0y * e1z - e0z * e1y;
    float ny = e0z * e1x - e0x * e1z;
    float nz = e0x * e1y - e0y * e1x;
    float nn = sqrtf(nx * nx + ny * ny + nz * nz);
    float inv = 1.0f / (nn + EPSF);
    nx *= inv; ny *= inv; nz *= inv;

    float cx = (a0x + a1x + a2x) * (1.0f / 3.0f);
    float cy = (a0y + a1y + a2y) * (1.0f / 3.0f);
    float cz = (a0z + a1z + a2z) * (1.0f / 3.0f);

    float pen = 0.0f;
#pragma unroll
    for (int v = 0; v < 3; v++) {
        float ux = P[3 * v + 0] - cx;
        float uy = P[3 * v + 1] - cy;
        float uz = P[3 * v + 2] - cz;
        float h = ux * nx + uy * ny + uz * nz;
        float wx = ux - h * nx;
        float wy = uy - h * ny;
        float wz = uz - h * nz;
        float r = sqrtf(wx * wx + wy * wy + wz * wz);
        float radial = fmaxf(1.0f - r / SIGMA, 0.0f);
        float depth = fmaxf(-h, 0.0f) + fmaxf(h, 0.0f) * expf(-h / SIGMA);
        float phi = radial * depth;
        pen += phi * phi;
    }
    return pen;
}

// ---------------------------------------------------------------------------
// Kernel B: warp-per-row ordered broad-phase scan (first 8 valid j ascending,
// matching stable top_k over the 0/1 validity matrix), then narrow phase.
// blockDim = 256 (8 warps = 8 rows per block). NUM_FACES % 8 == 0.
// ---------------------------------------------------------------------------
__global__ void __launch_bounds__(256) collide_kernel() {
    __shared__ int    s_list[8][MAXC];
    __shared__ double s_bsum;

    int lane = threadIdx.x & 31;
    int wid  = threadIdx.x >> 5;
    int row  = blockIdx.x * 8 + wid;

    if (threadIdx.x == 0) s_bsum = 0.0;
    __syncthreads();

    // receiver AABB + face ids (broadcast loads)
    float4 bmin = g_bbmin[row];
    float4 bmax = g_bbmax[row];
    int rf0 = __float_as_int(bmin.w);
    int rf1 = __float_as_int(bmax.w);
    int rf2 = g_f2[row];

    // ordered scan: first MAXC valid j ascending
    int found = 0;
    for (int base = 0; base < NUM_FACES && found < MAXC; base += 32) {
        int j = base + lane;
        bool ok = false;
        if (j < NUM_FACES) {
            float4 jmin = g_bbmin[j];
            float4 jmax = g_bbmax[j];
            ok = (bmin.x <= jmax.x) && (jmin.x <= bmax.x) &&
                 (bmin.y <= jmax.y) && (jmin.y <= bmax.y) &&
                 (bmin.z <= jmax.z) && (jmin.z <= bmax.z);
            if (ok) {
                int jf0 = __float_as_int(jmin.w);
                int jf1 = __float_as_int(jmax.w);
                int jf2 = g_f2[j];
                bool share = (rf0 == jf0) | (rf0 == jf1) | (rf0 == jf2) |
                             (rf1 == jf0) | (rf1 == jf1) | (rf1 == jf2) |
                             (rf2 == jf0) | (rf2 == jf1) | (rf2 == jf2);
                ok = !share;
            }
        }
        unsigned m = __ballot_sync(0xffffffffu, ok);
        int rank = found + __popc(m & ((1u << lane) - 1u));
        if (ok && rank < MAXC) s_list[wid][rank] = j;
        found += __popc(m);
    }
    if (found > MAXC) found = MAXC;
    __syncwarp();

    // narrow phase: lanes 0..15 -> (pair 0..7) x (direction 0..1)
    float pen = 0.0f;
    int pairIdx = lane >> 1;
    int dir = lane & 1;
    if (lane < 16 && pairIdx < found) {
        int jrow = s_list[wid][pairIdx];
        const float* src = &g_tri[(dir ? jrow : row) * 9];
        const float* pts = &g_tri[(dir ? row : jrow) * 9];
        pen = cone_penalty(src, pts);
    }
#pragma unroll
    for (int off = 16; off > 0; off >>= 1)
        pen += __shfl_xor_sync(0xffffffffu, pen, off);

    if (lane == 0 && pen != 0.0f) atomicAdd(&s_bsum, (double)pen);
    __syncthreads();
    if (threadIdx.x == 0) atomicAdd(&g_accum, s_bsum);
}

// ---------------------------------------------------------------------------
// Kernel C: finalize scalar output
// ---------------------------------------------------------------------------
__global__ void finalize_kernel(float* __restrict__ out) {
    out[0] = (float)g_accum;  // COLL_LOSS_WEIGHT = 1.0
}

extern "C" void kernel_launch(void* const* d_in, const int* in_sizes, int n_in,
                              void* d_out, int out_size) {
    const float* verts = (const float*)d_in[0];
    const int*   faces = (const int*)d_in[1];
    float*       out   = (float*)d_out;

    setup_kernel<<<(NUM_FACES + 255) / 256, 256>>>(verts, faces);
    collide_kernel<<<NUM_FACES / 8, 256>>>();
    finalize_kernel<<<1, 1>>>(out);
}